// round 11
// baseline (speedup 1.0000x reference)
#include <cuda_runtime.h>
#include <cuda_fp16.h>
#include <cstdint>
#include <math.h>

#define NN   50000
#define EE   400000
#define IND  256
#define HIDD 128
#define TT   3
#define RR   4
#define HH   8
#define DKK  16
#define NP   50432          // 394 blocks * 128
#define NTILE 394
#define NCHUNKS 30          // 6 adapt + 2*(3k + 3q + 3v + 3att)

// ---------------- scratch (static device globals) -----------------------------
__device__ __half d_h0h[NP*HIDD];
__device__ __half d_h1h[NP*HIDD];
__device__ __half d_aggh[NP*HIDD];
__device__ __half d_kh[NP*HIDD];
__device__ __half d_qh[NP*HIDD];
__device__ __half d_vh[NP*HIDD];
__device__ __half d_kvrel[(size_t)NP*RR*256];   // [p*4+r][0:128]=krel*pri/4, [128:256]=vrel
__device__ __half d_wpack[NCHUNKS*16384];
__device__ int   d_deg[NN];
__device__ int   d_off[NN+1];
__device__ int   d_cursor[NN];
__device__ int   d_epack[EE];
__device__ int   d_bagg[256];
__device__ int   d_bpfx[256];
__device__ int   d_bflag[256];
__device__ int   d_tcnt[TT];
__device__ int   d_topad[TT+1];
__device__ int   d_tcur2[TT];
__device__ int   d_nperm[NP];
__device__ int   d_iperm[NN];

// ---------------- helpers -------------------------------------------------------
__device__ __forceinline__ uint32_t smem_u32(const void* p) {
    uint32_t a;
    asm("{ .reg .u64 t; cvta.to.shared.u64 t, %1; cvt.u32.u64 %0, t; }" : "=r"(a) : "l"(p));
    return a;
}
__device__ __forceinline__ void ldmatrix_x4(uint32_t* r, uint32_t addr) {
    asm volatile("ldmatrix.sync.aligned.m8n8.x4.shared.b16 {%0,%1,%2,%3}, [%4];"
                 : "=r"(r[0]), "=r"(r[1]), "=r"(r[2]), "=r"(r[3]) : "r"(addr));
}
__device__ __forceinline__ void ldmatrix_x2(uint32_t* r, uint32_t addr) {
    asm volatile("ldmatrix.sync.aligned.m8n8.x2.shared.b16 {%0,%1}, [%2];"
                 : "=r"(r[0]), "=r"(r[1]) : "r"(addr));
}
__device__ __forceinline__ void mma16816h(float* d, const uint32_t* a, const uint32_t* b) {
    asm volatile("mma.sync.aligned.m16n8k16.row.col.f32.f16.f16.f32 "
                 "{%0,%1,%2,%3}, {%4,%5,%6,%7}, {%8,%9}, {%0,%1,%2,%3};"
                 : "+f"(d[0]), "+f"(d[1]), "+f"(d[2]), "+f"(d[3])
                 : "r"(a[0]), "r"(a[1]), "r"(a[2]), "r"(a[3]), "r"(b[0]), "r"(b[1]));
}
__device__ __forceinline__ float4 h4_to_f4(uint2 u) {
    __half2 a = *reinterpret_cast<__half2*>(&u.x);
    __half2 b = *reinterpret_cast<__half2*>(&u.y);
    float2 fa = __half22float2(a), fb = __half22float2(b);
    return make_float4(fa.x, fa.y, fb.x, fb.y);
}
__device__ __forceinline__ uint2 f4_to_h4(float4 f) {
    __half2 a = __floats2half2_rn(f.x, f.y);
    __half2 b = __floats2half2_rn(f.z, f.w);
    uint2 u;
    u.x = *reinterpret_cast<uint32_t*>(&a);
    u.y = *reinterpret_cast<uint32_t*>(&b);
    return u;
}

// ---------------- smem layout ----------------------------------------------------
#define SROW   136
#define OFF_A  0
#define OFF_B  34816
#define GSMEM  69632

// ---------------- setup kernels ------------------------------------------------
__global__ void k_init() {
    int i = blockIdx.x*blockDim.x + threadIdx.x;
    if (i < NP) d_nperm[i] = -1;
    if (i < NN) d_deg[i] = 0;
    if (i < TT) { d_tcnt[i] = 0; d_tcur2[i] = 0; }
    if (i < 256) d_bflag[i] = 0;
}
__global__ void k_count(const int* __restrict__ ntypes, const int* __restrict__ dst) {
    __shared__ int sh[TT];
    if (threadIdx.x < TT) sh[threadIdx.x] = 0;
    __syncthreads();
    int i = blockIdx.x*blockDim.x + threadIdx.x;
    if (i < NN) atomicAdd(&sh[ntypes[i]], 1);
    if (i < EE) atomicAdd(&d_deg[dst[i]], 1);
    __syncthreads();
    if (threadIdx.x < TT && sh[threadIdx.x]) atomicAdd(&d_tcnt[threadIdx.x], sh[threadIdx.x]);
}
// scatter nodes; inlines the type-offset computation (topad) per block
__global__ void k_scatter_nodes(const int* __restrict__ ntypes) {
    __shared__ int scnt[TT], sbase[TT], stopad[TT];
    if (threadIdx.x < TT) scnt[threadIdx.x] = 0;
    if (threadIdx.x == 0) {
        int c0 = d_tcnt[0], c1 = d_tcnt[1], c2 = d_tcnt[2];
        int p0 = ((c0 + 127) / 128) * 128;
        int p1 = ((c1 + 127) / 128) * 128;
        int p2 = ((c2 + 127) / 128) * 128;
        stopad[0] = 0; stopad[1] = p0; stopad[2] = p0 + p1;
        if (blockIdx.x == 0) {
            d_topad[0] = 0; d_topad[1] = p0; d_topad[2] = p0 + p1; d_topad[3] = p0 + p1 + p2;
        }
    }
    __syncthreads();
    int i = blockIdx.x*blockDim.x + threadIdx.x;
    int t = 0, myidx = 0;
    bool valid = (i < NN);
    if (valid) { t = ntypes[i]; myidx = atomicAdd(&scnt[t], 1); }
    __syncthreads();
    if (threadIdx.x < TT)
        sbase[threadIdx.x] = stopad[threadIdx.x] + atomicAdd(&d_tcur2[threadIdx.x], scnt[threadIdx.x]);
    __syncthreads();
    if (valid) {
        int p = sbase[t] + myidx;
        d_nperm[p] = i;
        d_iperm[i] = p;
    }
}
__device__ __forceinline__ int block_scan_incl(int x, int* wsum) {
    unsigned full = 0xffffffffu;
    int lane = threadIdx.x & 31, wid = threadIdx.x >> 5;
    int v = x;
    #pragma unroll
    for (int d = 1; d < 32; d <<= 1) {
        int t = __shfl_up_sync(full, v, d);
        if (lane >= d) v += t;
    }
    if (lane == 31) wsum[wid] = v;
    __syncthreads();
    if (threadIdx.x == 0) {
        int run = 0;
        #pragma unroll
        for (int w = 0; w < 8; w++) { int t = wsum[w]; wsum[w] = run; run += t; }
    }
    __syncthreads();
    return v + wsum[wid];
}
// single-pass exclusive scan of d_deg -> d_off/d_cursor via decoupled lookback
__global__ void k_scan_lb() {
    __shared__ int wsum[8];
    __shared__ int s_tot, s_pred;
    int b = blockIdx.x;
    int i = b*256 + threadIdx.x;
    int x = (i < NN) ? d_deg[i] : 0;
    int inc = block_scan_incl(x, wsum);
    if (threadIdx.x == 255) {
        s_tot = inc;
        d_bagg[b] = inc;
        __threadfence();
        atomicExch(&d_bflag[b], 1);
    }
    __syncthreads();
    if (threadIdx.x == 0) {
        int pred = 0;
        for (int j = b - 1; j >= 0; j--) {
            int f;
            do { f = *((volatile int*)&d_bflag[j]); } while (f == 0);
            if (f == 2) { pred += *((volatile int*)&d_bpfx[j]); break; }
            pred += *((volatile int*)&d_bagg[j]);
        }
        d_bpfx[b] = pred + s_tot;
        __threadfence();
        atomicExch(&d_bflag[b], 2);
        s_pred = pred;
        if (b == 0) d_off[NN] = EE;
    }
    __syncthreads();
    if (i < NN) {
        int v = s_pred + inc - x;
        d_off[i] = v;
        d_cursor[i] = v;
    }
}
__global__ void k_scatter_edges(const int* __restrict__ src, const int* __restrict__ dst,
                                const int* __restrict__ et) {
    int e = blockIdx.x*blockDim.x + threadIdx.x;
    if (e < EE) {
        int pos = atomicAdd(&d_cursor[dst[e]], 1);
        d_epack[pos] = (d_iperm[src[e]] << 2) | et[e];
    }
}

// ---------------- weight pack: fp32 -> transposed fp16 --------------------------
__global__ void k_wprep(const float* __restrict__ Wad, const float* __restrict__ Wk,
                        const float* __restrict__ Wq, const float* __restrict__ Wv,
                        const float* __restrict__ Wa) {
    int c = blockIdx.x;
    const float* W; int k0 = 0;
    if (c < 6) {
        int t = c >> 1; k0 = (c & 1) * 128;
        W = Wad + (size_t)t * 256 * 128;
    } else {
        int cc = c - 6;
        int l = cc / 12, rem = cc % 12, g = rem / 3, t = rem % 3;
        const float* Wg = (g == 0) ? Wk : (g == 1) ? Wq : (g == 2) ? Wv : Wa;
        W = Wg + (size_t)l * 3 * 128 * 128 + (size_t)t * 128 * 128;
    }
    __half* oh = d_wpack + (size_t)c * 16384;
    for (int i = threadIdx.x; i < 16384; i += 256) {
        int n = i >> 7, k = i & 127;
        oh[i] = __float2half_rn(W[(size_t)(k0 + k) * 128 + n]);
    }
}

// ---------------- GEMM building blocks -------------------------------------------
__device__ __forceinline__ void load_B(char* smem, int chunk) {
    const int tid = threadIdx.x;
    const uint4* bsrc = (const uint4*)(d_wpack + (size_t)chunk * 16384);
    #pragma unroll
    for (int i = 0; i < 8; i++) {
        int idx = tid + i * 256;
        int n = idx >> 4, k8g = idx & 15;
        *(uint4*)(smem + OFF_B + (uint32_t)(n * SROW + k8g * 8) * 2) = bsrc[idx];
    }
}
__device__ __forceinline__ void mma_accum(uint32_t sb, float acc[2][8][4]) {
    const int tid = threadIdx.x;
    const int wid = tid >> 5, lane = tid & 31;
    const int wm = wid & 3, wn = wid >> 2;
    const uint32_t aoff = (uint32_t)((wm*32 + (lane & 15)) * SROW + (lane >> 4) * 8) * 2;
    const int l16 = lane & 15;
    const uint32_t boff = (uint32_t)((wn*64 + (l16 & 7)) * SROW + (l16 >> 3) * 8) * 2;
    #pragma unroll
    for (int ks = 0; ks < 8; ks++) {
        uint32_t ah[2][4];
        #pragma unroll
        for (int mi = 0; mi < 2; mi++)
            ldmatrix_x4(ah[mi], sb + OFF_A + aoff + (uint32_t)(mi*16*SROW + ks*16) * 2);
        uint32_t bf[8][2];
        #pragma unroll
        for (int nj = 0; nj < 8; nj++)
            ldmatrix_x2(bf[nj], sb + OFF_B + boff + (uint32_t)(nj*8*SROW + ks*16) * 2);
        #pragma unroll
        for (int mi = 0; mi < 2; mi++)
            #pragma unroll
            for (int nj = 0; nj < 8; nj++)
                mma16816h(acc[mi][nj], ah[mi], bf[nj]);
    }
}
// fragment epilogue -> fp16 stage (at soff) with bias, optional tanh
template<int TANH>
__device__ __forceinline__ void frag_to_stage(char* smem, int soff, float acc[2][8][4],
                                              const float* __restrict__ bt) {
    const int tid = threadIdx.x;
    const int wid = tid >> 5, lane = tid & 31;
    const int wm = wid & 3, wn = wid >> 2;
    __half* hstage = (__half*)(smem + soff);
    #pragma unroll
    for (int mi = 0; mi < 2; mi++) {
        #pragma unroll
        for (int nj = 0; nj < 8; nj++) {
            int row = wm*32 + mi*16 + (lane >> 2);
            int col = wn*64 + nj*8 + 2*(lane & 3);
            float b0 = __ldg(&bt[col]), b1 = __ldg(&bt[col+1]);
            float v0 = acc[mi][nj][0] + b0;
            float v1 = acc[mi][nj][1] + b1;
            float v2 = acc[mi][nj][2] + b0;
            float v3 = acc[mi][nj][3] + b1;
            if (TANH) { v0 = tanhf(v0); v1 = tanhf(v1); v2 = tanhf(v2); v3 = tanhf(v3); }
            *(__half2*)(hstage + row * SROW + col)     = __floats2half2_rn(v0, v1);
            *(__half2*)(hstage + (row+8) * SROW + col) = __floats2half2_rn(v2, v3);
        }
    }
}
// coalesced copy fp16 stage -> global [128][128]
__device__ __forceinline__ void stage_to_global(char* smem, int soff, __half* dst) {
    const int tid = threadIdx.x;
    const __half* hstage = (const __half*)(smem + soff);
    #pragma unroll
    for (int i = 0; i < 8; i++) {
        int idx = tid + i * 256;
        int row = idx >> 4, seg = idx & 15;
        uint4 v = *(const uint4*)(hstage + row * SROW + seg * 8);
        *(uint4*)(dst + (size_t)row * 128 + seg * 8) = v;
    }
}
// k/q/v GEMM loop: A tile resident in A region; writes kh/qh/vh
__device__ __forceinline__ void kqv_phase(char* smem, uint32_t sb, int base, int t, int l,
                                          const float* __restrict__ bk,
                                          const float* __restrict__ bq,
                                          const float* __restrict__ bv) {
    for (int s = 0; s < 3; s++) {
        __syncthreads();
        load_B(smem, 6 + l*12 + s*3 + t);
        __syncthreads();
        float acc[2][8][4];
        #pragma unroll
        for (int mi = 0; mi < 2; mi++)
            #pragma unroll
            for (int nj = 0; nj < 8; nj++)
                #pragma unroll
                for (int e = 0; e < 4; e++) acc[mi][nj][e] = 0.f;
        mma_accum(sb, acc);
        __syncthreads();
        const float* bsel = (s == 0) ? bk : (s == 1) ? bq : bv;
        frag_to_stage<0>(smem, OFF_B, acc, bsel + l*TT*HIDD + t*128);
        __syncthreads();
        __half* dst = ((s == 0) ? d_kh : (s == 1) ? d_qh : d_vh) + (size_t)base * 128;
        stage_to_global(smem, OFF_B, dst);
    }
}

// ---------------- fused adapt + kqv (layer 0) ------------------------------------
__global__ void __launch_bounds__(256,2)
k_adapt_kqv0(const float* __restrict__ x, const float* __restrict__ bad,
             const float* __restrict__ bk, const float* __restrict__ bq,
             const float* __restrict__ bv) {
    extern __shared__ char smem[];
    const uint32_t sb = smem_u32(smem);
    const int tid = threadIdx.x;
    const int base = blockIdx.x * 128;
    const int t = (base >= d_topad[1]) + (base >= d_topad[2]);

    float acc[2][8][4];
    #pragma unroll
    for (int mi = 0; mi < 2; mi++)
        #pragma unroll
        for (int nj = 0; nj < 8; nj++)
            #pragma unroll
            for (int e = 0; e < 4; e++) acc[mi][nj][e] = 0.f;

    for (int kc = 0; kc < 2; kc++) {
        if (kc > 0) __syncthreads();
        load_B(smem, t*2 + kc);
        #pragma unroll
        for (int i = 0; i < 8; i++) {
            int gi = tid + i * 256;
            int row = gi >> 4;
            int k8 = (gi & 15) * 8;
            float v[8];
            int rn = d_nperm[base + row];
            if (rn >= 0) {
                const float4* ap = (const float4*)(x + (size_t)rn * IND + kc*128 + k8);
                float4 a0 = ap[0], a1 = ap[1];
                v[0]=a0.x; v[1]=a0.y; v[2]=a0.z; v[3]=a0.w;
                v[4]=a1.x; v[5]=a1.y; v[6]=a1.z; v[7]=a1.w;
            } else {
                #pragma unroll
                for (int j = 0; j < 8; j++) v[j] = 0.f;
            }
            union { __half b[8]; uint4 u; } ph;
            #pragma unroll
            for (int j = 0; j < 8; j++) ph.b[j] = __float2half_rn(v[j]);
            *(uint4*)(smem + OFF_A + (uint32_t)(row * SROW + k8) * 2) = ph.u;
        }
        __syncthreads();
        mma_accum(sb, acc);
    }
    __syncthreads();          // mma reads of A done; overwrite A with tanh result
    frag_to_stage<1>(smem, OFF_A, acc, bad + t*128);
    __syncthreads();
    stage_to_global(smem, OFF_A, d_h0h + (size_t)base * 128);  // residual for combine1
    kqv_phase(smem, sb, base, t, 0, bk, bq, bv);
}

// ---------------- fused att0 + LN/ReLU + kqv (layer 1) ---------------------------
__global__ void __launch_bounds__(256,2)
k_att_kqv1(const float* __restrict__ ba, const float* __restrict__ skip,
           const float* __restrict__ gamma, const float* __restrict__ beta,
           const float* __restrict__ bk, const float* __restrict__ bq,
           const float* __restrict__ bv) {
    extern __shared__ char smem[];
    const uint32_t sb = smem_u32(smem);
    const int tid = threadIdx.x;
    const int wid = tid >> 5, lane = tid & 31;
    const int base = blockIdx.x * 128;
    const int t = (base >= d_topad[1]) + (base >= d_topad[2]);
    const unsigned full = 0xffffffffu;

    load_B(smem, 15 + t);     // layer-0 att chunk
    // A-stage: GELU(aggh)
    #pragma unroll
    for (int i = 0; i < 8; i++) {
        int gi = tid + i * 256;
        int row = gi >> 4;
        int k8 = (gi & 15) * 8;
        uint4 raw = *(const uint4*)(d_aggh + (size_t)(base + row) * 128 + k8);
        union { __half b[8]; uint4 u; } ph;
        const __half2* hp = reinterpret_cast<const __half2*>(&raw);
        #pragma unroll
        for (int j = 0; j < 4; j++) {
            float2 f2 = __half22float2(hp[j]);
            f2.x = 0.5f * f2.x * (1.0f + erff(f2.x * 0.70710678118654752f));
            f2.y = 0.5f * f2.y * (1.0f + erff(f2.y * 0.70710678118654752f));
            ph.b[2*j]   = __float2half_rn(f2.x);
            ph.b[2*j+1] = __float2half_rn(f2.y);
        }
        *(uint4*)(smem + OFF_A + (uint32_t)(row * SROW + k8) * 2) = ph.u;
    }
    __syncthreads();
    float acc[2][8][4];
    #pragma unroll
    for (int mi = 0; mi < 2; mi++)
        #pragma unroll
        for (int nj = 0; nj < 8; nj++)
            #pragma unroll
            for (int e = 0; e < 4; e++) acc[mi][nj][e] = 0.f;
    mma_accum(sb, acc);
    __syncthreads();
    frag_to_stage<0>(smem, OFF_A, acc, ba + t*128);   // trans tile -> A region
    __syncthreads();

    // LN/ReLU phase: warp handles 16 rows; combine with fp16 residual h0h
    {
        float alpha = 1.0f / (1.0f + __expf(-__ldg(&skip[t])));
        float ia = 1.0f - alpha;
        float4 g4 = *(const float4*)(gamma + t*128 + lane*4);
        float4 b4 = *(const float4*)(beta  + t*128 + lane*4);
        __half* hstage = (__half*)(smem + OFF_A);
        #pragma unroll
        for (int i = 0; i < 16; i++) {
            int row = wid*16 + i;
            float4 tr = h4_to_f4(*(const uint2*)(hstage + row * SROW + lane*4));
            float4 h0 = h4_to_f4(*(const uint2*)(d_h0h + (size_t)(base+row)*128 + lane*4));
            float4 o;
            o.x = tr.x*alpha + h0.x*ia;
            o.y = tr.y*alpha + h0.y*ia;
            o.z = tr.z*alpha + h0.z*ia;
            o.w = tr.w*alpha + h0.w*ia;
            float sm = o.x + o.y + o.z + o.w;
            float sq = o.x*o.x + o.y*o.y + o.z*o.z + o.w*o.w;
            #pragma unroll
            for (int d = 16; d; d >>= 1) {
                sm += __shfl_xor_sync(full, sm, d);
                sq += __shfl_xor_sync(full, sq, d);
            }
            float mean = sm * (1.0f/128.0f);
            float var  = sq * (1.0f/128.0f) - mean*mean;
            float rstd = rsqrtf(var + 1e-5f);
            float4 y;
            y.x = fmaxf((o.x-mean)*rstd*g4.x + b4.x, 0.f);
            y.y = fmaxf((o.y-mean)*rstd*g4.y + b4.y, 0.f);
            y.z = fmaxf((o.z-mean)*rstd*g4.z + b4.z, 0.f);
            y.w = fmaxf((o.w-mean)*rstd*g4.w + b4.w, 0.f);
            uint2 yh = f4_to_h4(y);
            *(uint2*)(hstage + row * SROW + lane*4) = yh;                    // A := h1 tile
            *(uint2*)(d_h1h + (size_t)(base+row)*128 + lane*4) = yh;         // residual for final
        }
    }
    kqv_phase(smem, sb, base, t, 1, bk, bq, bv);
}

// ---------------- final att GEMM (layer 1) + combine2 -> out ---------------------
__global__ void __launch_bounds__(256,2)
k_att1_final(const float* __restrict__ ba, const float* __restrict__ skip,
             float* __restrict__ out) {
    extern __shared__ char smem[];
    const uint32_t sb = smem_u32(smem);
    const int tid = threadIdx.x;
    const int wid = tid >> 5, lane = tid & 31;
    const int base = blockIdx.x * 128;
    const int t = (base >= d_topad[1]) + (base >= d_topad[2]);

    load_B(smem, 27 + t);     // layer-1 att chunk
    #pragma unroll
    for (int i = 0; i < 8; i++) {
        int gi = tid + i * 256;
        int row = gi >> 4;
        int k8 = (gi & 15) * 8;
        uint4 raw = *(const uint4*)(d_aggh + (size_t)(base + row) * 128 + k8);
        union { __half b[8]; uint4 u; } ph;
        const __half2* hp = reinterpret_cast<const __half2*>(&raw);
        #pragma unroll
        for (int j = 0; j < 4; j++) {
            float2 f2 = __half22float2(hp[j]);
            f2.x = 0.5f * f2.x * (1.0f + erff(f2.x * 0.70710678118654752f));
            f2.y = 0.5f * f2.y * (1.0f + erff(f2.y * 0.70710678118654752f));
            ph.b[2*j]   = __float2half_rn(f2.x);
            ph.b[2*j+1] = __float2half_rn(f2.y);
        }
        *(uint4*)(smem + OFF_A + (uint32_t)(row * SROW + k8) * 2) = ph.u;
    }
    __syncthreads();
    float acc[2][8][4];
    #pragma unroll
    for (int mi = 0; mi < 2; mi++)
        #pragma unroll
        for (int nj = 0; nj < 8; nj++)
            #pragma unroll
            for (int e = 0; e < 4; e++) acc[mi][nj][e] = 0.f;
    mma_accum(sb, acc);
    __syncthreads();

    // fp32 stage (whole smem)
    float* stage = (float*)smem;              // [128][132]
    const float* bt = ba + TT*HIDD + t*128;   // layer-1 bias
    {
        const int wm = wid & 3, wn = wid >> 2;
        #pragma unroll
        for (int mi = 0; mi < 2; mi++) {
            #pragma unroll
            for (int nj = 0; nj < 8; nj++) {
                int row = wm*32 + mi*16 + (lane >> 2);
                int col = wn*64 + nj*8 + 2*(lane & 3);
                float b0 = __ldg(&bt[col]), b1 = __ldg(&bt[col+1]);
                stage[row*132 + col]     = acc[mi][nj][0] + b0;
                stage[row*132 + col + 1] = acc[mi][nj][1] + b1;
                stage[(row+8)*132 + col]     = acc[mi][nj][2] + b0;
                stage[(row+8)*132 + col + 1] = acc[mi][nj][3] + b1;
            }
        }
    }
    __syncthreads();
    float alpha = 1.0f / (1.0f + __expf(-__ldg(&skip[TT + t])));
    float ia = 1.0f - alpha;
    #pragma unroll
    for (int i = 0; i < 16; i++) {
        int row = wid*16 + i;
        float4 tr = *(const float4*)(stage + row*132 + lane*4);
        float4 hx = h4_to_f4(*(const uint2*)(d_h1h + (size_t)(base+row)*128 + lane*4));
        float4 o;
        o.x = tr.x*alpha + hx.x*ia;
        o.y = tr.y*alpha + hx.y*ia;
        o.z = tr.z*alpha + hx.z*ia;
        o.w = tr.w*alpha + hx.w*ia;
        int node = d_nperm[base + row];
        if (node >= 0)
            *(float4*)(out + (size_t)node*128 + lane*4) = o;
    }
}

// ---------------- per-node relation transforms (fp16 in/out, FFMA) -------------
__global__ void k_reltrans(const float* __restrict__ Ratt, const float* __restrict__ Rmsg,
                           const float* __restrict__ pri) {
    const int slot = blockIdx.y;
    const int r = slot >> 1;
    const bool isV = slot & 1;
    const __half* srcv = isV ? d_vh : d_kh;
    const float* Wh = (isV ? Rmsg : Ratt) + r*HH*DKK*DKK;

    const int lane = threadIdx.x & 31;
    const int wid  = threadIdx.x >> 5;
    const int h = lane >> 2;
    const int f0 = (lane & 3) * 4;
    const float* Wp = Wh + h*256;
    const float pscale = isV ? 1.0f : (__ldg(&pri[r*HH + h]) * 0.25f);

    float4 w[16];
    #pragma unroll
    for (int d = 0; d < 16; d++) w[d] = *(const float4*)(Wp + d*16 + f0);

    const int wpb = blockDim.x >> 5;
    for (int n = blockIdx.x*wpb + wid; n < NP; n += gridDim.x*wpb) {
        uint4 raw0 = *(const uint4*)(srcv + (size_t)n*128 + h*16);
        uint4 raw1 = *(const uint4*)(srcv + (size_t)n*128 + h*16 + 8);
        float f[16];
        {
            const __half2* hp0 = reinterpret_cast<const __half2*>(&raw0);
            const __half2* hp1 = reinterpret_cast<const __half2*>(&raw1);
            #pragma unroll
            for (int j = 0; j < 4; j++) {
                float2 t2 = __half22float2(hp0[j]);
                f[2*j] = t2.x; f[2*j+1] = t2.y;
                float2 u2 = __half22float2(hp1[j]);
                f[8+2*j] = u2.x; f[8+2*j+1] = u2.y;
            }
        }
        float4 acc = make_float4(0.f,0.f,0.f,0.f);
        #pragma unroll
        for (int d = 0; d < 16; d++) {
            acc.x = fmaf(f[d], w[d].x, acc.x);
            acc.y = fmaf(f[d], w[d].y, acc.y);
            acc.z = fmaf(f[d], w[d].z, acc.z);
            acc.w = fmaf(f[d], w[d].w, acc.w);
        }
        if (!isV) { acc.x *= pscale; acc.y *= pscale; acc.z *= pscale; acc.w *= pscale; }
        *(uint2*)(d_kvrel + ((size_t)n*RR + r)*256 + (isV ? 128 : 0) + h*16 + f0) = f4_to_h4(acc);
    }
}

// ---------------- edge phase: warp-per-dst, online softmax, unroll 4 ------------
__device__ __forceinline__ void edge_step(uint2 kr, uint2 vr, const float4 q4,
                                          float& m, float& s, float4& acc) {
    const unsigned full = 0xffffffffu;
    float4 k4 = h4_to_f4(kr);
    float4 v4 = h4_to_f4(vr);
    float p = q4.x*k4.x + q4.y*k4.y + q4.z*k4.z + q4.w*k4.w;
    p += __shfl_xor_sync(full, p, 1);
    p += __shfl_xor_sync(full, p, 2);
    float mn = fmaxf(m, p);
    float corr = __expf(m - mn);
    float w = __expf(p - mn);
    s = s*corr + w;
    acc.x = fmaf(w, v4.x, acc.x*corr);
    acc.y = fmaf(w, v4.y, acc.y*corr);
    acc.z = fmaf(w, v4.z, acc.z*corr);
    acc.w = fmaf(w, v4.w, acc.w*corr);
    m = mn;
}

__global__ void k_edge() {
    const int n = (blockIdx.x*blockDim.x + threadIdx.x) >> 5;
    if (n >= NN) return;
    const int lane = threadIdx.x & 31;

    const int ip = d_iperm[n];
    float4 q4 = h4_to_f4(*(const uint2*)(d_qh + (size_t)ip*128 + lane*4));
    const int beg = d_off[n], end = d_off[n+1];

    float m = -1e30f, s = 0.f;
    float4 acc = make_float4(0.f,0.f,0.f,0.f);

    int e = beg;
    for (; e + 3 < end; e += 4) {
        uint2 k[4], v[4];
        #pragma unroll
        for (int j = 0; j < 4; j++) {
            const __half* b = d_kvrel + (size_t)d_epack[e + j] * 256;
            k[j] = *(const uint2*)(b + lane*4);
            v[j] = *(const uint2*)(b + 128 + lane*4);
        }
        #pragma unroll
        for (int j = 0; j < 4; j++) edge_step(k[j], v[j], q4, m, s, acc);
    }
    for (; e < end; e++) {
        const __half* b = d_kvrel + (size_t)d_epack[e] * 256;
        uint2 k0 = *(const uint2*)(b + lane*4);
        uint2 v0 = *(const uint2*)(b + 128 + lane*4);
        edge_step(k0, v0, q4, m, s, acc);
    }
    float inv = 1.0f / fmaxf(s, 1e-9f);
    acc.x *= inv; acc.y *= inv; acc.z *= inv; acc.w *= inv;
    *(uint2*)(d_aggh + (size_t)ip*128 + lane*4) = f4_to_h4(acc);
}

// ---------------- launch --------------------------------------------------------
extern "C" void kernel_launch(void* const* d_in, const int* in_sizes, int n_in,
                              void* d_out, int out_size) {
    const float* x      = (const float*)d_in[0];
    const int*   ntypes = (const int*)d_in[1];
    const int*   ei     = (const int*)d_in[2];
    const int*   et     = (const int*)d_in[3];
    const float* Wad    = (const float*)d_in[4];
    const float* bad    = (const float*)d_in[5];
    const float* Wk     = (const float*)d_in[6];
    const float* bk     = (const float*)d_in[7];
    const float* Wq     = (const float*)d_in[8];
    const float* bq     = (const float*)d_in[9];
    const float* Wv     = (const float*)d_in[10];
    const float* bv     = (const float*)d_in[11];
    const float* Wa     = (const float*)d_in[12];
    const float* ba     = (const float*)d_in[13];
    const float* pri    = (const float*)d_in[14];
    const float* ratt   = (const float*)d_in[15];
    const float* rmsg   = (const float*)d_in[16];
    const float* skip   = (const float*)d_in[17];
    const float* gamma  = (const float*)d_in[18];
    const float* beta   = (const float*)d_in[19];
    float* out = (float*)d_out;

    const int* srcA = ei;
    const int* dstA = ei + EE;

    cudaFuncSetAttribute(k_adapt_kqv0, cudaFuncAttributeMaxDynamicSharedMemorySize, GSMEM);
    cudaFuncSetAttribute(k_att_kqv1,   cudaFuncAttributeMaxDynamicSharedMemorySize, GSMEM);
    cudaFuncSetAttribute(k_att1_final, cudaFuncAttributeMaxDynamicSharedMemorySize, GSMEM);

    const int WARP_BLK = (NN*32 + 255) / 256;
    const int LP = RR*HH;
    const int LR = RR*HH*DKK*DKK;

    k_wprep<<<NCHUNKS, 256>>>(Wad, Wk, Wq, Wv, Wa);
    k_init<<<(NP+255)/256, 256>>>();
    k_count<<<(EE+255)/256, 256>>>(ntypes, dstA);
    k_scatter_nodes<<<(NN+255)/256, 256>>>(ntypes);
    k_scan_lb<<<(NN+255)/256, 256>>>();
    k_scatter_edges<<<(EE+255)/256, 256>>>(srcA, dstA, et);

    // layer 0
    k_adapt_kqv0<<<NTILE, 256, GSMEM>>>(x, bad, bk, bq, bv);
    k_reltrans<<<dim3(296, 8), 256>>>(ratt, rmsg, pri);
    k_edge<<<WARP_BLK, 256>>>();
    // layer 0 att + LN + layer 1 kqv
    k_att_kqv1<<<NTILE, 256, GSMEM>>>(ba, skip, gamma, beta, bk, bq, bv);
    k_reltrans<<<dim3(296, 8), 256>>>(ratt + (size_t)LR, rmsg + (size_t)LR, pri + LP);
    k_edge<<<WARP_BLK, 256>>>();
    k_att1_final<<<NTILE, 256, GSMEM>>>(ba, skip, out);
}